// round 1
// baseline (speedup 1.0000x reference)
#include <cuda_runtime.h>
#include <math_constants.h>

// ChamferDistance: x1,x2 = [B=8, N=M=8192, 3] fp32.
// out = [ loss (1) | dist1 (B*N) | dist2 (B*M) ]  (reference tuple order)
//
// d(n,m) = n1[n] + (n2[m] - 2*dot(a,b));  dist = max(n1 + min_m e, 0)
// Inner loop uses packed fma.rn.f32x2: 3 packed FFMA per 2 pairs.
// B-tile cached in smem pre-duplicated so packed operands need no MOV replication.

constexpr int Bc = 8;
constexpr int Nc = 8192;
constexpr int Mc = 8192;
constexpr int THREADS = 256;
constexpr int PTS = 4;                       // A-points per thread (2 packed pairs)
constexpr int TILE_N = THREADS * PTS;        // 1024
constexpr int TILE_M = 1024;                 // B-points per smem tile (32 KB dup'd)

__device__ __forceinline__ unsigned long long pk2(float lo, float hi) {
    unsigned long long r;
    asm("mov.b64 %0, {%1, %2};" : "=l"(r) : "f"(lo), "f"(hi));
    return r;
}
__device__ __forceinline__ unsigned long long ffma2(unsigned long long a,
                                                    unsigned long long b,
                                                    unsigned long long c) {
    unsigned long long d;
    asm("fma.rn.f32x2 %0, %1, %2, %3;" : "=l"(d) : "l"(a), "l"(b), "l"(c));
    return d;
}
__device__ __forceinline__ void upk2(unsigned long long v, float& lo, float& hi) {
    asm("mov.b64 {%0, %1}, %2;" : "=f"(lo), "=f"(hi) : "l"(v));
}

__global__ void __launch_bounds__(THREADS)
chamfer_pass_kernel(const float* __restrict__ x1, const float* __restrict__ x2,
                    float* __restrict__ dist1, float* __restrict__ dist2)
{
    // duplicated layout per B-point: {bx2,bx2, by2,by2, bz2,bz2, n2,n2}
    __shared__ __align__(16) float tile[TILE_M * 8];

    const int dir = blockIdx.z;
    const float* __restrict__ P = (dir == 0) ? x1 : x2;   // "A" cloud
    const float* __restrict__ Q = (dir == 0) ? x2 : x1;   // "B" cloud
    float* __restrict__ outd = (dir == 0) ? dist1 : dist2;

    const int b = blockIdx.y;
    const int tid = threadIdx.x;
    const int nbase = blockIdx.x * TILE_N;

    float ax[PTS], ay[PTS], az[PTS];
#pragma unroll
    for (int k = 0; k < PTS; k++) {
        const int n = nbase + k * THREADS + tid;
        const float* p = P + ((size_t)b * Nc + n) * 3;
        ax[k] = p[0]; ay[k] = p[1]; az[k] = p[2];
    }

    unsigned long long axp[2], ayp[2], azp[2];
#pragma unroll
    for (int p = 0; p < 2; p++) {
        axp[p] = pk2(ax[2 * p], ax[2 * p + 1]);
        ayp[p] = pk2(ay[2 * p], ay[2 * p + 1]);
        azp[p] = pk2(az[2 * p], az[2 * p + 1]);
    }

    float emin0 = CUDART_INF_F, emin1 = CUDART_INF_F;
    float emin2 = CUDART_INF_F, emin3 = CUDART_INF_F;

    for (int t0 = 0; t0 < Mc; t0 += TILE_M) {
        __syncthreads();
        // fill duplicated tile
#pragma unroll
        for (int j = tid; j < TILE_M; j += THREADS) {
            const float* q = Q + ((size_t)b * Mc + t0 + j) * 3;
            const float bx = q[0], by = q[1], bz = q[2];
            const float n2 = fmaf(bx, bx, fmaf(by, by, bz * bz));
            float4* s = reinterpret_cast<float4*>(&tile[j * 8]);
            s[0] = make_float4(-2.0f * bx, -2.0f * bx, -2.0f * by, -2.0f * by);
            s[1] = make_float4(-2.0f * bz, -2.0f * bz, n2, n2);
        }
        __syncthreads();

#pragma unroll 8
        for (int j = 0; j < TILE_M; j++) {
            const ulonglong2* sp = reinterpret_cast<const ulonglong2*>(&tile[j * 8]);
            const ulonglong2 v0 = sp[0];   // v0.x = {bx2,bx2}, v0.y = {by2,by2}
            const ulonglong2 v1 = sp[1];   // v1.x = {bz2,bz2}, v1.y = {n2,n2}

            unsigned long long e0 = ffma2(axp[0], v0.x, v1.y);
            e0 = ffma2(ayp[0], v0.y, e0);
            e0 = ffma2(azp[0], v1.x, e0);

            unsigned long long e1 = ffma2(axp[1], v0.x, v1.y);
            e1 = ffma2(ayp[1], v0.y, e1);
            e1 = ffma2(azp[1], v1.x, e1);

            float f0, f1, f2, f3;
            upk2(e0, f0, f1);
            upk2(e1, f2, f3);
            emin0 = fminf(emin0, f0);
            emin1 = fminf(emin1, f1);
            emin2 = fminf(emin2, f2);
            emin3 = fminf(emin3, f3);
        }
    }

    const float em[PTS] = {emin0, emin1, emin2, emin3};
#pragma unroll
    for (int k = 0; k < PTS; k++) {
        const float n1 = fmaf(ax[k], ax[k], fmaf(ay[k], ay[k], az[k] * az[k]));
        const int n = nbase + k * THREADS + tid;
        outd[(size_t)b * Nc + n] = fmaxf(n1 + em[k], 0.0f);
    }
}

__global__ void __launch_bounds__(1024)
loss_kernel(float* __restrict__ out)
{
    __shared__ float red[1024];
    const int tid = threadIdx.x;
    const int total = 2 * Bc * Nc;   // 131072
    float s = 0.0f;
    for (int i = tid; i < total; i += 1024) s += out[1 + i];
    red[tid] = s;
    __syncthreads();
    for (int w = 512; w > 0; w >>= 1) {
        if (tid < w) red[tid] += red[tid + w];
        __syncthreads();
    }
    if (tid == 0) out[0] = red[0] * (1.0f / (float)(Bc * Nc));
}

extern "C" void kernel_launch(void* const* d_in, const int* in_sizes, int n_in,
                              void* d_out, int out_size)
{
    const float* x1 = (const float*)d_in[0];
    const float* x2 = (const float*)d_in[1];
    float* out = (float*)d_out;
    float* dist1 = out + 1;
    float* dist2 = out + 1 + Bc * Nc;

    dim3 grid(Nc / TILE_N, Bc, 2);
    chamfer_pass_kernel<<<grid, THREADS>>>(x1, x2, dist1, dist2);
    loss_kernel<<<1, 1024>>>(out);
}

// round 2
// speedup vs baseline: 1.1532x; 1.1532x over previous
#include <cuda_runtime.h>
#include <math_constants.h>

// ChamferDistance: x1,x2 = [B=8, N=M=8192, 3] fp32.
// out = [ loss (1) | dist1 (B*N) | dist2 (B*M) ]
//
// R2: PTS=8 per thread (4 packed f32x2 pairs), M dimension split 2-ways across
// CTAs, combined with int-punned atomicMin (valid: clamped dists >= 0, IEEE
// order == signed-int order). dist arrays pre-set to 0x7F7F7F7F (3.39e38)
// sentinel via cudaMemsetAsync. Loss reduced by 2-stage deterministic kernel.

constexpr int Bc = 8;
constexpr int Nc = 8192;
constexpr int Mc = 8192;
constexpr int THREADS = 256;
constexpr int PTS = 8;                       // A-points per thread (4 packed pairs)
constexpr int NPAIR = PTS / 2;               // 4
constexpr int TILE_N = THREADS * PTS;        // 2048
constexpr int TILE_M = 1024;                 // B-points per smem tile (32 KB dup'd)
constexpr int M_SPLIT = 2;
constexpr int M_HALF = Mc / M_SPLIT;         // 4096

__device__ __forceinline__ unsigned long long pk2(float lo, float hi) {
    unsigned long long r;
    asm("mov.b64 %0, {%1, %2};" : "=l"(r) : "f"(lo), "f"(hi));
    return r;
}
__device__ __forceinline__ unsigned long long ffma2(unsigned long long a,
                                                    unsigned long long b,
                                                    unsigned long long c) {
    unsigned long long d;
    asm("fma.rn.f32x2 %0, %1, %2, %3;" : "=l"(d) : "l"(a), "l"(b), "l"(c));
    return d;
}
__device__ __forceinline__ void upk2(unsigned long long v, float& lo, float& hi) {
    asm("mov.b64 {%0, %1}, %2;" : "=f"(lo), "=f"(hi) : "l"(v));
}

__global__ void __launch_bounds__(THREADS)
chamfer_pass_kernel(const float* __restrict__ x1, const float* __restrict__ x2,
                    float* __restrict__ dist1, float* __restrict__ dist2)
{
    // duplicated layout per B-point: {bx2,bx2, by2,by2, bz2,bz2, n2,n2}
    __shared__ __align__(16) float tile[TILE_M * 8];

    const int dir  = blockIdx.z >> 1;
    const int half = blockIdx.z & 1;
    const float* __restrict__ P = (dir == 0) ? x1 : x2;   // "A" cloud
    const float* __restrict__ Q = (dir == 0) ? x2 : x1;   // "B" cloud
    float* __restrict__ outd = (dir == 0) ? dist1 : dist2;

    const int b = blockIdx.y;
    const int tid = threadIdx.x;
    const int nbase = blockIdx.x * TILE_N;

    // Load A points, pack coords and |a|^2 into f32x2 registers.
    unsigned long long axp[NPAIR], ayp[NPAIR], azp[NPAIR], n1p[NPAIR];
#pragma unroll
    for (int p = 0; p < NPAIR; p++) {
        const int k0 = 2 * p, k1 = 2 * p + 1;
        const int n0 = nbase + k0 * THREADS + tid;
        const int n1i = nbase + k1 * THREADS + tid;
        const float* p0 = P + ((size_t)b * Nc + n0) * 3;
        const float* p1 = P + ((size_t)b * Nc + n1i) * 3;
        const float a0x = p0[0], a0y = p0[1], a0z = p0[2];
        const float a1x = p1[0], a1y = p1[1], a1z = p1[2];
        axp[p] = pk2(a0x, a1x);
        ayp[p] = pk2(a0y, a1y);
        azp[p] = pk2(a0z, a1z);
        n1p[p] = pk2(fmaf(a0x, a0x, fmaf(a0y, a0y, a0z * a0z)),
                     fmaf(a1x, a1x, fmaf(a1y, a1y, a1z * a1z)));
    }

    float emin[PTS];
#pragma unroll
    for (int k = 0; k < PTS; k++) emin[k] = CUDART_INF_F;

    const int mbeg = half * M_HALF;
    for (int t0 = mbeg; t0 < mbeg + M_HALF; t0 += TILE_M) {
        __syncthreads();
#pragma unroll
        for (int j = tid; j < TILE_M; j += THREADS) {
            const float* q = Q + ((size_t)b * Mc + t0 + j) * 3;
            const float bx = q[0], by = q[1], bz = q[2];
            const float n2 = fmaf(bx, bx, fmaf(by, by, bz * bz));
            float4* s = reinterpret_cast<float4*>(&tile[j * 8]);
            s[0] = make_float4(-2.0f * bx, -2.0f * bx, -2.0f * by, -2.0f * by);
            s[1] = make_float4(-2.0f * bz, -2.0f * bz, n2, n2);
        }
        __syncthreads();

#pragma unroll 4
        for (int j = 0; j < TILE_M; j++) {
            const ulonglong2* sp = reinterpret_cast<const ulonglong2*>(&tile[j * 8]);
            const ulonglong2 v0 = sp[0];   // {bx2,bx2}, {by2,by2}
            const ulonglong2 v1 = sp[1];   // {bz2,bz2}, {n2,n2}

#pragma unroll
            for (int p = 0; p < NPAIR; p++) {
                unsigned long long e = ffma2(axp[p], v0.x, v1.y);
                e = ffma2(ayp[p], v0.y, e);
                e = ffma2(azp[p], v1.x, e);
                float flo, fhi;
                upk2(e, flo, fhi);
                emin[2 * p]     = fminf(emin[2 * p], flo);
                emin[2 * p + 1] = fminf(emin[2 * p + 1], fhi);
            }
        }
    }

    // Combine with the other M-half via int-punned atomicMin (clamped, >= 0).
#pragma unroll
    for (int p = 0; p < NPAIR; p++) {
        float n1lo, n1hi;
        upk2(n1p[p], n1lo, n1hi);
        const int n0 = nbase + (2 * p) * THREADS + tid;
        const int n1i = nbase + (2 * p + 1) * THREADS + tid;
        const float d0 = fmaxf(n1lo + emin[2 * p], 0.0f);
        const float d1 = fmaxf(n1hi + emin[2 * p + 1], 0.0f);
        atomicMin((int*)&outd[(size_t)b * Nc + n0], __float_as_int(d0));
        atomicMin((int*)&outd[(size_t)b * Nc + n1i], __float_as_int(d1));
    }
}

// ---- deterministic 2-stage loss reduction ----
__device__ float g_partials[128];

__global__ void __launch_bounds__(256)
sum_stage1(const float* __restrict__ dists)   // dists = out+1, length 2*B*N
{
    __shared__ float red[256];
    const int tid = threadIdx.x;
    const int base = blockIdx.x * 1024;
    float s = 0.0f;
#pragma unroll
    for (int i = 0; i < 4; i++) s += dists[base + i * 256 + tid];
    red[tid] = s;
    __syncthreads();
    for (int w = 128; w > 0; w >>= 1) {
        if (tid < w) red[tid] += red[tid + w];
        __syncthreads();
    }
    if (tid == 0) g_partials[blockIdx.x] = red[0];
}

__global__ void __launch_bounds__(128)
sum_stage2(float* __restrict__ out)
{
    __shared__ float red[128];
    const int tid = threadIdx.x;
    red[tid] = g_partials[tid];
    __syncthreads();
    for (int w = 64; w > 0; w >>= 1) {
        if (tid < w) red[tid] += red[tid + w];
        __syncthreads();
    }
    if (tid == 0) out[0] = red[0] * (1.0f / (float)(Bc * Nc));
}

extern "C" void kernel_launch(void* const* d_in, const int* in_sizes, int n_in,
                              void* d_out, int out_size)
{
    const float* x1 = (const float*)d_in[0];
    const float* x2 = (const float*)d_in[1];
    float* out = (float*)d_out;
    float* dist1 = out + 1;
    float* dist2 = out + 1 + Bc * Nc;

    // Sentinel-fill dist arrays: 0x7F7F7F7F = 3.39e38 > any real sq-distance.
    cudaMemsetAsync(out + 1, 0x7F, (size_t)2 * Bc * Nc * sizeof(float));

    dim3 grid(Nc / TILE_N, Bc, 2 * M_SPLIT);   // (4, 8, 4) = 128 CTAs
    chamfer_pass_kernel<<<grid, THREADS>>>(x1, x2, dist1, dist2);

    sum_stage1<<<128, 256>>>(out + 1);
    sum_stage2<<<1, 128>>>(out);
}

// round 3
// speedup vs baseline: 1.2870x; 1.1161x over previous
#include <cuda_runtime.h>
#include <math_constants.h>

// ChamferDistance: x1,x2 = [B=8, N=M=8192, 3] fp32.
// out = [ loss (1) | dist1 (B*N) | dist2 (B*M) ]
//
// R3: 512-thread CTAs, grid = 148 (one per SM, 16 warps/SM). Work = 1024 equal
// tiles: 32 A-chunks (dirxbatchxnchunk, 4096 A-pts) x 32 M-slices (256 B-pts).
// CTA i owns contiguous tiles [i*1024/148, (i+1)*1024/148) -> 98.8% SM balance.
// emin accumulated in regs across a CTA's slices of one A-chunk; flushed via
// int-punned atomicMin on A-chunk change (<=2 flushes/CTA). Sentinel 0x7F fill.

constexpr int Bc = 8;
constexpr int Nc = 8192;
constexpr int Mc = 8192;
constexpr int THREADS = 512;
constexpr int PTS = 8;                        // A-points per thread (4 packed pairs)
constexpr int NPAIR = PTS / 2;                // 4
constexpr int TILE_N = THREADS * PTS;         // 4096
constexpr int NCHUNKS = Nc / TILE_N;          // 2
constexpr int TILE_M = 256;                   // B-points per tile (8 KB dup'd)
constexpr int MSLICES = Mc / TILE_M;          // 32
constexpr int NACH = 2 * Bc * NCHUNKS;        // 32 A-chunks
constexpr int NTILES = NACH * MSLICES;        // 1024
constexpr int GRID = 148;

__device__ __forceinline__ unsigned long long pk2(float lo, float hi) {
    unsigned long long r;
    asm("mov.b64 %0, {%1, %2};" : "=l"(r) : "f"(lo), "f"(hi));
    return r;
}
__device__ __forceinline__ unsigned long long ffma2(unsigned long long a,
                                                    unsigned long long b,
                                                    unsigned long long c) {
    unsigned long long d;
    asm("fma.rn.f32x2 %0, %1, %2, %3;" : "=l"(d) : "l"(a), "l"(b), "l"(c));
    return d;
}
__device__ __forceinline__ void upk2(unsigned long long v, float& lo, float& hi) {
    asm("mov.b64 {%0, %1}, %2;" : "=f"(lo), "=f"(hi) : "l"(v));
}

__global__ void __launch_bounds__(THREADS)
chamfer_pass_kernel(const float* __restrict__ x1, const float* __restrict__ x2,
                    float* __restrict__ dist1, float* __restrict__ dist2)
{
    // duplicated layout per B-point: {bx2,bx2, by2,by2, bz2,bz2, n2,n2}
    __shared__ __align__(16) float tile[TILE_M * 8];

    const int tid = threadIdx.x;
    const int bid = blockIdx.x;
    const int tstart = (bid * NTILES) / GRID;
    const int tend   = ((bid + 1) * NTILES) / GRID;

    // per-A-chunk state
    unsigned long long axp[NPAIR], ayp[NPAIR], azp[NPAIR], n1p[NPAIR];
    float emin[PTS];
    int cur_ach = -1;
    int cur_dir = 0, cur_b = 0, cur_nbase = 0;

    for (int t = tstart; t < tend; t++) {
        const int ach = t >> 5;          // [0,32)
        const int ms  = t & (MSLICES - 1);

        if (ach != cur_ach) {
            // flush previous A-chunk
            if (cur_ach >= 0) {
                float* __restrict__ outd = cur_dir ? dist2 : dist1;
#pragma unroll
                for (int p = 0; p < NPAIR; p++) {
                    float n1lo, n1hi;
                    upk2(n1p[p], n1lo, n1hi);
                    const int n0 = cur_nbase + (2 * p) * THREADS + tid;
                    const int n1i = cur_nbase + (2 * p + 1) * THREADS + tid;
                    const float d0 = fmaxf(n1lo + emin[2 * p], 0.0f);
                    const float d1 = fmaxf(n1hi + emin[2 * p + 1], 0.0f);
                    atomicMin((int*)&outd[(size_t)cur_b * Nc + n0], __float_as_int(d0));
                    atomicMin((int*)&outd[(size_t)cur_b * Nc + n1i], __float_as_int(d1));
                }
            }
            // load new A-chunk
            cur_ach = ach;
            const int db = ach >> 1;                 // dir*8 + b
            cur_dir = db >> 3;
            cur_b = db & 7;
            cur_nbase = (ach & 1) * TILE_N;
            const float* __restrict__ P = cur_dir ? x2 : x1;
#pragma unroll
            for (int p = 0; p < NPAIR; p++) {
                const int n0 = cur_nbase + (2 * p) * THREADS + tid;
                const int n1i = cur_nbase + (2 * p + 1) * THREADS + tid;
                const float* p0 = P + ((size_t)cur_b * Nc + n0) * 3;
                const float* p1 = P + ((size_t)cur_b * Nc + n1i) * 3;
                const float a0x = p0[0], a0y = p0[1], a0z = p0[2];
                const float a1x = p1[0], a1y = p1[1], a1z = p1[2];
                axp[p] = pk2(a0x, a1x);
                ayp[p] = pk2(a0y, a1y);
                azp[p] = pk2(a0z, a1z);
                n1p[p] = pk2(fmaf(a0x, a0x, fmaf(a0y, a0y, a0z * a0z)),
                             fmaf(a1x, a1x, fmaf(a1y, a1y, a1z * a1z)));
            }
#pragma unroll
            for (int k = 0; k < PTS; k++) emin[k] = CUDART_INF_F;
        }

        // fill B tile for this M-slice (guard reuse, then fill, then publish)
        const float* __restrict__ Q = cur_dir ? x1 : x2;
        __syncthreads();
        if (tid < TILE_M) {
            const int j = tid;
            const float* q = Q + ((size_t)cur_b * Mc + ms * TILE_M + j) * 3;
            const float bx = q[0], by = q[1], bz = q[2];
            const float n2 = fmaf(bx, bx, fmaf(by, by, bz * bz));
            float4* s = reinterpret_cast<float4*>(&tile[j * 8]);
            s[0] = make_float4(-2.0f * bx, -2.0f * bx, -2.0f * by, -2.0f * by);
            s[1] = make_float4(-2.0f * bz, -2.0f * bz, n2, n2);
        }
        __syncthreads();

#pragma unroll 4
        for (int j = 0; j < TILE_M; j++) {
            const ulonglong2* sp = reinterpret_cast<const ulonglong2*>(&tile[j * 8]);
            const ulonglong2 v0 = sp[0];   // {bx2,bx2}, {by2,by2}
            const ulonglong2 v1 = sp[1];   // {bz2,bz2}, {n2,n2}

#pragma unroll
            for (int p = 0; p < NPAIR; p++) {
                unsigned long long e = ffma2(axp[p], v0.x, v1.y);
                e = ffma2(ayp[p], v0.y, e);
                e = ffma2(azp[p], v1.x, e);
                float flo, fhi;
                upk2(e, flo, fhi);
                emin[2 * p]     = fminf(emin[2 * p], flo);
                emin[2 * p + 1] = fminf(emin[2 * p + 1], fhi);
            }
        }
    }

    // final flush
    if (cur_ach >= 0) {
        float* __restrict__ outd = cur_dir ? dist2 : dist1;
#pragma unroll
        for (int p = 0; p < NPAIR; p++) {
            float n1lo, n1hi;
            upk2(n1p[p], n1lo, n1hi);
            const int n0 = cur_nbase + (2 * p) * THREADS + tid;
            const int n1i = cur_nbase + (2 * p + 1) * THREADS + tid;
            const float d0 = fmaxf(n1lo + emin[2 * p], 0.0f);
            const float d1 = fmaxf(n1hi + emin[2 * p + 1], 0.0f);
            atomicMin((int*)&outd[(size_t)cur_b * Nc + n0], __float_as_int(d0));
            atomicMin((int*)&outd[(size_t)cur_b * Nc + n1i], __float_as_int(d1));
        }
    }
}

// ---- deterministic 2-stage loss reduction ----
__device__ float g_partials[128];

__global__ void __launch_bounds__(256)
sum_stage1(const float* __restrict__ dists)   // dists = out+1, length 2*B*N
{
    __shared__ float red[256];
    const int tid = threadIdx.x;
    const int base = blockIdx.x * 1024;
    float s = 0.0f;
#pragma unroll
    for (int i = 0; i < 4; i++) s += dists[base + i * 256 + tid];
    red[tid] = s;
    __syncthreads();
    for (int w = 128; w > 0; w >>= 1) {
        if (tid < w) red[tid] += red[tid + w];
        __syncthreads();
    }
    if (tid == 0) g_partials[blockIdx.x] = red[0];
}

__global__ void __launch_bounds__(128)
sum_stage2(float* __restrict__ out)
{
    __shared__ float red[128];
    const int tid = threadIdx.x;
    red[tid] = g_partials[tid];
    __syncthreads();
    for (int w = 64; w > 0; w >>= 1) {
        if (tid < w) red[tid] += red[tid + w];
        __syncthreads();
    }
    if (tid == 0) out[0] = red[0] * (1.0f / (float)(Bc * Nc));
}

extern "C" void kernel_launch(void* const* d_in, const int* in_sizes, int n_in,
                              void* d_out, int out_size)
{
    const float* x1 = (const float*)d_in[0];
    const float* x2 = (const float*)d_in[1];
    float* out = (float*)d_out;
    float* dist1 = out + 1;
    float* dist2 = out + 1 + Bc * Nc;

    // Sentinel-fill dist arrays: 0x7F7F7F7F = 3.39e38 > any real sq-distance.
    cudaMemsetAsync(out + 1, 0x7F, (size_t)2 * Bc * Nc * sizeof(float));

    chamfer_pass_kernel<<<GRID, THREADS>>>(x1, x2, dist1, dist2);

    sum_stage1<<<128, 256>>>(out + 1);
    sum_stage2<<<1, 128>>>(out);
}

// round 4
// speedup vs baseline: 1.3690x; 1.0637x over previous
#include <cuda_runtime.h>
#include <math_constants.h>

// ChamferDistance: x1,x2 = [B=8, N=M=8192, 3] fp32.
// out = [ loss (1) | dist1 (B*N) | dist2 (B*M) ]
//
// R4: B-points packed in pairs into f32x2 lanes (A duplicated in registers),
// halving LDS traffic; explicit next-iteration smem prefetch; even/odd min
// accumulators merged at flush. Persistent 148-CTA grid, 512 thr, tile-balanced
// 1024-way; cross-CTA combine via int-punned atomicMin on 0x7F sentinel.

constexpr int Bc = 8;
constexpr int Nc = 8192;
constexpr int Mc = 8192;
constexpr int THREADS = 512;
constexpr int PTS = 8;                        // A-points per thread (each dup'd)
constexpr int TILE_N = THREADS * PTS;         // 4096
constexpr int NCHUNKS = Nc / TILE_N;          // 2
constexpr int TILE_M = 256;                   // B-points per slice
constexpr int JP = TILE_M / 2;                // 128 j-pairs
constexpr int MSLICES = Mc / TILE_M;          // 32
constexpr int NACH = 2 * Bc * NCHUNKS;        // 32 A-chunks
constexpr int NTILES = NACH * MSLICES;        // 1024
constexpr int GRID = 148;

__device__ __forceinline__ unsigned long long pk2(float lo, float hi) {
    unsigned long long r;
    asm("mov.b64 %0, {%1, %2};" : "=l"(r) : "f"(lo), "f"(hi));
    return r;
}
__device__ __forceinline__ unsigned long long ffma2(unsigned long long a,
                                                    unsigned long long b,
                                                    unsigned long long c) {
    unsigned long long d;
    asm("fma.rn.f32x2 %0, %1, %2, %3;" : "=l"(d) : "l"(a), "l"(b), "l"(c));
    return d;
}
__device__ __forceinline__ void upk2(unsigned long long v, float& lo, float& hi) {
    asm("mov.b64 {%0, %1}, %2;" : "=f"(lo), "=f"(hi) : "l"(v));
}

__global__ void __launch_bounds__(THREADS)
chamfer_pass_kernel(const float* __restrict__ x1, const float* __restrict__ x2,
                    float* __restrict__ dist1, float* __restrict__ dist2)
{
    // per j-pair: {bx2_e,bx2_o, by2_e,by2_o, bz2_e,bz2_o, n2_e,n2_o}  (32 B)
    __shared__ __align__(16) float tile[JP * 8];

    const int tid = threadIdx.x;
    const int bid = blockIdx.x;
    const int tstart = (bid * NTILES) / GRID;
    const int tend   = ((bid + 1) * NTILES) / GRID;

    // per-A-chunk state: coords duplicated into both f32x2 halves
    unsigned long long axp[PTS], ayp[PTS], azp[PTS];
    float n1s[PTS];
    float eminE[PTS], eminO[PTS];
    int cur_ach = -1;
    int cur_dir = 0, cur_b = 0, cur_nbase = 0;

    for (int t = tstart; t < tend; t++) {
        const int ach = t >> 5;          // [0,32)
        const int ms  = t & (MSLICES - 1);

        if (ach != cur_ach) {
            if (cur_ach >= 0) {          // flush previous A-chunk
                float* __restrict__ outd = cur_dir ? dist2 : dist1;
#pragma unroll
                for (int k = 0; k < PTS; k++) {
                    const int n = cur_nbase + k * THREADS + tid;
                    const float e = fminf(eminE[k], eminO[k]);
                    const float d = fmaxf(n1s[k] + e, 0.0f);
                    atomicMin((int*)&outd[(size_t)cur_b * Nc + n], __float_as_int(d));
                }
            }
            cur_ach = ach;
            const int db = ach >> 1;                 // dir*8 + b
            cur_dir = db >> 3;
            cur_b = db & 7;
            cur_nbase = (ach & 1) * TILE_N;
            const float* __restrict__ P = cur_dir ? x2 : x1;
#pragma unroll
            for (int k = 0; k < PTS; k++) {
                const int n = cur_nbase + k * THREADS + tid;
                const float* p = P + ((size_t)cur_b * Nc + n) * 3;
                const float ax = p[0], ay = p[1], az = p[2];
                axp[k] = pk2(ax, ax);
                ayp[k] = pk2(ay, ay);
                azp[k] = pk2(az, az);
                n1s[k] = fmaf(ax, ax, fmaf(ay, ay, az * az));
                eminE[k] = CUDART_INF_F;
                eminO[k] = CUDART_INF_F;
            }
        }

        // fill B tile for this M-slice (2 B-points per filling thread)
        const float* __restrict__ Q = cur_dir ? x1 : x2;
        __syncthreads();
        if (tid < JP) {
            const float* q = Q + ((size_t)cur_b * Mc + ms * TILE_M + 2 * tid) * 3;
            const float bxe = q[0], bye = q[1], bze = q[2];
            const float bxo = q[3], byo = q[4], bzo = q[5];
            const float n2e = fmaf(bxe, bxe, fmaf(bye, bye, bze * bze));
            const float n2o = fmaf(bxo, bxo, fmaf(byo, byo, bzo * bzo));
            float4* s = reinterpret_cast<float4*>(&tile[tid * 8]);
            s[0] = make_float4(-2.0f * bxe, -2.0f * bxo, -2.0f * bye, -2.0f * byo);
            s[1] = make_float4(-2.0f * bze, -2.0f * bzo, n2e, n2o);
        }
        __syncthreads();

        // inner loop with explicit next-pair prefetch
        const ulonglong2* sp = reinterpret_cast<const ulonglong2*>(tile);
        ulonglong2 c0 = sp[0];
        ulonglong2 c1 = sp[1];
#pragma unroll 2
        for (int jj = 0; jj < JP; jj++) {
            ulonglong2 n0, n1v;
            if (jj + 1 < JP) {
                n0 = sp[2 * (jj + 1)];
                n1v = sp[2 * (jj + 1) + 1];
            }
            // c0.x={bx2_e,bx2_o}  c0.y={by2_e,by2_o}  c1.x={bz2_e,bz2_o}  c1.y={n2_e,n2_o}
#pragma unroll
            for (int k = 0; k < PTS; k++) {
                unsigned long long e = ffma2(axp[k], c0.x, c1.y);
                e = ffma2(ayp[k], c0.y, e);
                e = ffma2(azp[k], c1.x, e);
                float flo, fhi;
                upk2(e, flo, fhi);
                eminE[k] = fminf(eminE[k], flo);
                eminO[k] = fminf(eminO[k], fhi);
            }
            c0 = n0;
            c1 = n1v;
        }
    }

    if (cur_ach >= 0) {                  // final flush
        float* __restrict__ outd = cur_dir ? dist2 : dist1;
#pragma unroll
        for (int k = 0; k < PTS; k++) {
            const int n = cur_nbase + k * THREADS + tid;
            const float e = fminf(eminE[k], eminO[k]);
            const float d = fmaxf(n1s[k] + e, 0.0f);
            atomicMin((int*)&outd[(size_t)cur_b * Nc + n], __float_as_int(d));
        }
    }
}

// ---- deterministic 2-stage loss reduction ----
__device__ float g_partials[128];

__global__ void __launch_bounds__(256)
sum_stage1(const float* __restrict__ dists)   // dists = out+1, length 2*B*N
{
    __shared__ float red[256];
    const int tid = threadIdx.x;
    const int base = blockIdx.x * 1024;
    float s = 0.0f;
#pragma unroll
    for (int i = 0; i < 4; i++) s += dists[base + i * 256 + tid];
    red[tid] = s;
    __syncthreads();
    for (int w = 128; w > 0; w >>= 1) {
        if (tid < w) red[tid] += red[tid + w];
        __syncthreads();
    }
    if (tid == 0) g_partials[blockIdx.x] = red[0];
}

__global__ void __launch_bounds__(128)
sum_stage2(float* __restrict__ out)
{
    __shared__ float red[128];
    const int tid = threadIdx.x;
    red[tid] = g_partials[tid];
    __syncthreads();
    for (int w = 64; w > 0; w >>= 1) {
        if (tid < w) red[tid] += red[tid + w];
        __syncthreads();
    }
    if (tid == 0) out[0] = red[0] * (1.0f / (float)(Bc * Nc));
}

extern "C" void kernel_launch(void* const* d_in, const int* in_sizes, int n_in,
                              void* d_out, int out_size)
{
    const float* x1 = (const float*)d_in[0];
    const float* x2 = (const float*)d_in[1];
    float* out = (float*)d_out;
    float* dist1 = out + 1;
    float* dist2 = out + 1 + Bc * Nc;

    // Sentinel-fill dist arrays: 0x7F7F7F7F = 3.39e38 > any real sq-distance.
    cudaMemsetAsync(out + 1, 0x7F, (size_t)2 * Bc * Nc * sizeof(float));

    chamfer_pass_kernel<<<GRID, THREADS>>>(x1, x2, dist1, dist2);

    sum_stage1<<<128, 256>>>(out + 1);
    sum_stage2<<<1, 128>>>(out);
}

// round 5
// speedup vs baseline: 1.4497x; 1.0590x over previous
#include <cuda_runtime.h>
#include <math_constants.h>

// ChamferDistance: x1,x2 = [B=8, N=M=8192, 3] fp32.
// out = [ loss (1) | dist1 (B*N) | dist2 (B*M) ]
//
// R5: occupancy push. PTS=4 (2 packed B-pair lanes per A-pt), 512 thr,
// __launch_bounds__(512,2) -> <=64 regs -> 2 CTAs/SM -> 32 warps/SM.
// Grid = 296 (2 per SM). Work = 2048 equal tiles: 64 A-chunks (2048 A-pts)
// x 32 M-slices (256 B-pts). Contiguous tile ranges per CTA; emin in regs,
// flushed via int-punned atomicMin on A-chunk change. 0x7F sentinel fill.

constexpr int Bc = 8;
constexpr int Nc = 8192;
constexpr int Mc = 8192;
constexpr int THREADS = 512;
constexpr int PTS = 4;                        // A-points per thread (each dup'd)
constexpr int TILE_N = THREADS * PTS;         // 2048
constexpr int NCHUNKS = Nc / TILE_N;          // 4
constexpr int TILE_M = 256;                   // B-points per slice
constexpr int JP = TILE_M / 2;                // 128 j-pairs
constexpr int MSLICES = Mc / TILE_M;          // 32
constexpr int NACH = 2 * Bc * NCHUNKS;        // 64 A-chunks
constexpr int NTILES = NACH * MSLICES;        // 2048
constexpr int GRID = 296;                     // 2 CTAs per SM

__device__ __forceinline__ unsigned long long pk2(float lo, float hi) {
    unsigned long long r;
    asm("mov.b64 %0, {%1, %2};" : "=l"(r) : "f"(lo), "f"(hi));
    return r;
}
__device__ __forceinline__ unsigned long long ffma2(unsigned long long a,
                                                    unsigned long long b,
                                                    unsigned long long c) {
    unsigned long long d;
    asm("fma.rn.f32x2 %0, %1, %2, %3;" : "=l"(d) : "l"(a), "l"(b), "l"(c));
    return d;
}
__device__ __forceinline__ void upk2(unsigned long long v, float& lo, float& hi) {
    asm("mov.b64 {%0, %1}, %2;" : "=f"(lo), "=f"(hi) : "l"(v));
}

__global__ void __launch_bounds__(THREADS, 2)
chamfer_pass_kernel(const float* __restrict__ x1, const float* __restrict__ x2,
                    float* __restrict__ dist1, float* __restrict__ dist2)
{
    // per j-pair: {bx2_e,bx2_o, by2_e,by2_o, bz2_e,bz2_o, n2_e,n2_o}  (32 B)
    __shared__ __align__(16) float tile[JP * 8];

    const int tid = threadIdx.x;
    const int bid = blockIdx.x;
    const int tstart = (bid * NTILES) / GRID;
    const int tend   = ((bid + 1) * NTILES) / GRID;

    // per-A-chunk state: coords duplicated into both f32x2 halves
    unsigned long long axp[PTS], ayp[PTS], azp[PTS];
    float n1s[PTS];
    float eminE[PTS], eminO[PTS];
    int cur_ach = -1;
    int cur_dir = 0, cur_b = 0, cur_nbase = 0;

    for (int t = tstart; t < tend; t++) {
        const int ach = t >> 5;          // [0,64)
        const int ms  = t & (MSLICES - 1);

        if (ach != cur_ach) {
            if (cur_ach >= 0) {          // flush previous A-chunk
                float* __restrict__ outd = cur_dir ? dist2 : dist1;
#pragma unroll
                for (int k = 0; k < PTS; k++) {
                    const int n = cur_nbase + k * THREADS + tid;
                    const float e = fminf(eminE[k], eminO[k]);
                    const float d = fmaxf(n1s[k] + e, 0.0f);
                    atomicMin((int*)&outd[(size_t)cur_b * Nc + n], __float_as_int(d));
                }
            }
            cur_ach = ach;
            const int db = ach >> 2;                 // dir*8 + b
            cur_dir = db >> 3;
            cur_b = db & 7;
            cur_nbase = (ach & 3) * TILE_N;
            const float* __restrict__ P = cur_dir ? x2 : x1;
#pragma unroll
            for (int k = 0; k < PTS; k++) {
                const int n = cur_nbase + k * THREADS + tid;
                const float* p = P + ((size_t)cur_b * Nc + n) * 3;
                const float ax = p[0], ay = p[1], az = p[2];
                axp[k] = pk2(ax, ax);
                ayp[k] = pk2(ay, ay);
                azp[k] = pk2(az, az);
                n1s[k] = fmaf(ax, ax, fmaf(ay, ay, az * az));
                eminE[k] = CUDART_INF_F;
                eminO[k] = CUDART_INF_F;
            }
        }

        // fill B tile for this M-slice (2 B-points per filling thread)
        const float* __restrict__ Q = cur_dir ? x1 : x2;
        __syncthreads();
        if (tid < JP) {
            const float* q = Q + ((size_t)cur_b * Mc + ms * TILE_M + 2 * tid) * 3;
            const float bxe = q[0], bye = q[1], bze = q[2];
            const float bxo = q[3], byo = q[4], bzo = q[5];
            const float n2e = fmaf(bxe, bxe, fmaf(bye, bye, bze * bze));
            const float n2o = fmaf(bxo, bxo, fmaf(byo, byo, bzo * bzo));
            float4* s = reinterpret_cast<float4*>(&tile[tid * 8]);
            s[0] = make_float4(-2.0f * bxe, -2.0f * bxo, -2.0f * bye, -2.0f * byo);
            s[1] = make_float4(-2.0f * bze, -2.0f * bzo, n2e, n2o);
        }
        __syncthreads();

        const ulonglong2* sp = reinterpret_cast<const ulonglong2*>(tile);
#pragma unroll 4
        for (int jj = 0; jj < JP; jj++) {
            const ulonglong2 c0 = sp[2 * jj];       // {bx2_e,bx2_o} {by2_e,by2_o}
            const ulonglong2 c1 = sp[2 * jj + 1];   // {bz2_e,bz2_o} {n2_e,n2_o}
#pragma unroll
            for (int k = 0; k < PTS; k++) {
                unsigned long long e = ffma2(axp[k], c0.x, c1.y);
                e = ffma2(ayp[k], c0.y, e);
                e = ffma2(azp[k], c1.x, e);
                float flo, fhi;
                upk2(e, flo, fhi);
                eminE[k] = fminf(eminE[k], flo);
                eminO[k] = fminf(eminO[k], fhi);
            }
        }
    }

    if (cur_ach >= 0) {                  // final flush
        float* __restrict__ outd = cur_dir ? dist2 : dist1;
#pragma unroll
        for (int k = 0; k < PTS; k++) {
            const int n = cur_nbase + k * THREADS + tid;
            const float e = fminf(eminE[k], eminO[k]);
            const float d = fmaxf(n1s[k] + e, 0.0f);
            atomicMin((int*)&outd[(size_t)cur_b * Nc + n], __float_as_int(d));
        }
    }
}

// ---- deterministic 2-stage loss reduction ----
__device__ float g_partials[128];

__global__ void __launch_bounds__(256)
sum_stage1(const float* __restrict__ dists)   // dists = out+1, length 2*B*N
{
    __shared__ float red[256];
    const int tid = threadIdx.x;
    const int base = blockIdx.x * 1024;
    float s = 0.0f;
#pragma unroll
    for (int i = 0; i < 4; i++) s += dists[base + i * 256 + tid];
    red[tid] = s;
    __syncthreads();
    for (int w = 128; w > 0; w >>= 1) {
        if (tid < w) red[tid] += red[tid + w];
        __syncthreads();
    }
    if (tid == 0) g_partials[blockIdx.x] = red[0];
}

__global__ void __launch_bounds__(128)
sum_stage2(float* __restrict__ out)
{
    __shared__ float red[128];
    const int tid = threadIdx.x;
    red[tid] = g_partials[tid];
    __syncthreads();
    for (int w = 64; w > 0; w >>= 1) {
        if (tid < w) red[tid] += red[tid + w];
        __syncthreads();
    }
    if (tid == 0) out[0] = red[0] * (1.0f / (float)(Bc * Nc));
}

extern "C" void kernel_launch(void* const* d_in, const int* in_sizes, int n_in,
                              void* d_out, int out_size)
{
    const float* x1 = (const float*)d_in[0];
    const float* x2 = (const float*)d_in[1];
    float* out = (float*)d_out;
    float* dist1 = out + 1;
    float* dist2 = out + 1 + Bc * Nc;

    // Sentinel-fill dist arrays: 0x7F7F7F7F = 3.39e38 > any real sq-distance.
    cudaMemsetAsync(out + 1, 0x7F, (size_t)2 * Bc * Nc * sizeof(float));

    chamfer_pass_kernel<<<GRID, THREADS>>>(x1, x2, dist1, dist2);

    sum_stage1<<<128, 256>>>(out + 1);
    sum_stage2<<<1, 128>>>(out);
}

// round 6
// speedup vs baseline: 1.5093x; 1.0411x over previous
#include <cuda_runtime.h>
#include <math_constants.h>

// ChamferDistance: x1,x2 = [B=8, N=M=8192, 3] fp32.
// out = [ loss (1) | dist1 (B*N) | dist2 (B*M) ]
//
// R6: double-buffered B tile, ONE __syncthreads per M-slice round
// (bar; fill next buf; compute current buf). PTS=4, 512 thr, 2 CTAs/SM
// (grid 296), 2048 balanced tiles, int-punned atomicMin combine, 0x7F fill.

constexpr int Bc = 8;
constexpr int Nc = 8192;
constexpr int Mc = 8192;
constexpr int THREADS = 512;
constexpr int PTS = 4;                        // A-points per thread (each dup'd)
constexpr int TILE_N = THREADS * PTS;         // 2048
constexpr int NCHUNKS = Nc / TILE_N;          // 4
constexpr int TILE_M = 256;                   // B-points per slice
constexpr int JP = TILE_M / 2;                // 128 j-pairs
constexpr int MSLICES = Mc / TILE_M;          // 32
constexpr int NACH = 2 * Bc * NCHUNKS;        // 64 A-chunks
constexpr int NTILES = NACH * MSLICES;        // 2048
constexpr int GRID = 296;                     // 2 CTAs per SM

__device__ __forceinline__ unsigned long long pk2(float lo, float hi) {
    unsigned long long r;
    asm("mov.b64 %0, {%1, %2};" : "=l"(r) : "f"(lo), "f"(hi));
    return r;
}
__device__ __forceinline__ unsigned long long ffma2(unsigned long long a,
                                                    unsigned long long b,
                                                    unsigned long long c) {
    unsigned long long d;
    asm("fma.rn.f32x2 %0, %1, %2, %3;" : "=l"(d) : "l"(a), "l"(b), "l"(c));
    return d;
}
__device__ __forceinline__ void upk2(unsigned long long v, float& lo, float& hi) {
    asm("mov.b64 {%0, %1}, %2;" : "=f"(lo), "=f"(hi) : "l"(v));
}

// decode tile id -> (dir, b, nbase, ms)
__device__ __forceinline__ void decode_tile(int t, int& dir, int& b, int& nbase, int& ms) {
    const int ach = t >> 5;          // [0,64)
    ms = t & (MSLICES - 1);
    const int db = ach >> 2;         // dir*8 + b
    dir = db >> 3;
    b = db & 7;
    nbase = (ach & 3) * TILE_N;
}

__global__ void __launch_bounds__(THREADS, 2)
chamfer_pass_kernel(const float* __restrict__ x1, const float* __restrict__ x2,
                    float* __restrict__ dist1, float* __restrict__ dist2)
{
    // 2 buffers; per j-pair: {bx2_e,bx2_o, by2_e,by2_o, bz2_e,bz2_o, n2_e,n2_o}
    __shared__ __align__(16) float tile[2][JP * 8];

    const int tid = threadIdx.x;
    const int bid = blockIdx.x;
    const int tstart = (bid * NTILES) / GRID;
    const int tend   = ((bid + 1) * NTILES) / GRID;

    unsigned long long axp[PTS], ayp[PTS], azp[PTS];
    float n1s[PTS];
    float eminE[PTS], eminO[PTS];
    int cur_ach = -1;
    int cur_dir = 0, cur_b = 0, cur_nbase = 0;

    // prologue: fill buffer 0 with tile tstart
    {
        int dir, b, nbase, ms;
        decode_tile(tstart, dir, b, nbase, ms);
        const float* __restrict__ Q = dir ? x1 : x2;
        if (tid < JP) {
            const float* q = Q + ((size_t)b * Mc + ms * TILE_M + 2 * tid) * 3;
            const float bxe = q[0], bye = q[1], bze = q[2];
            const float bxo = q[3], byo = q[4], bzo = q[5];
            const float n2e = fmaf(bxe, bxe, fmaf(bye, bye, bze * bze));
            const float n2o = fmaf(bxo, bxo, fmaf(byo, byo, bzo * bzo));
            float4* s = reinterpret_cast<float4*>(&tile[0][tid * 8]);
            s[0] = make_float4(-2.0f * bxe, -2.0f * bxo, -2.0f * bye, -2.0f * byo);
            s[1] = make_float4(-2.0f * bze, -2.0f * bzo, n2e, n2o);
        }
    }

    for (int t = tstart; t < tend; t++) {
        const int buf = (t - tstart) & 1;

        // single barrier per round: orders this round's fill (done last round)
        // before compute, and last round's compute before we refill its buffer.
        __syncthreads();

        // fill NEXT tile into the other buffer
        if (t + 1 < tend && tid < JP) {
            int ndir, nb, nnbase, nms;
            decode_tile(t + 1, ndir, nb, nnbase, nms);
            const float* __restrict__ Q = ndir ? x1 : x2;
            const float* q = Q + ((size_t)nb * Mc + nms * TILE_M + 2 * tid) * 3;
            const float bxe = q[0], bye = q[1], bze = q[2];
            const float bxo = q[3], byo = q[4], bzo = q[5];
            const float n2e = fmaf(bxe, bxe, fmaf(bye, bye, bze * bze));
            const float n2o = fmaf(bxo, bxo, fmaf(byo, byo, bzo * bzo));
            float4* s = reinterpret_cast<float4*>(&tile[buf ^ 1][tid * 8]);
            s[0] = make_float4(-2.0f * bxe, -2.0f * bxo, -2.0f * bye, -2.0f * byo);
            s[1] = make_float4(-2.0f * bze, -2.0f * bzo, n2e, n2o);
        }

        // A-chunk management for CURRENT tile
        const int ach = t >> 5;
        if (ach != cur_ach) {
            if (cur_ach >= 0) {          // flush previous A-chunk
                float* __restrict__ outd = cur_dir ? dist2 : dist1;
#pragma unroll
                for (int k = 0; k < PTS; k++) {
                    const int n = cur_nbase + k * THREADS + tid;
                    const float e = fminf(eminE[k], eminO[k]);
                    const float d = fmaxf(n1s[k] + e, 0.0f);
                    atomicMin((int*)&outd[(size_t)cur_b * Nc + n], __float_as_int(d));
                }
            }
            cur_ach = ach;
            int ms_un;
            decode_tile(t, cur_dir, cur_b, cur_nbase, ms_un);
            const float* __restrict__ P = cur_dir ? x2 : x1;
#pragma unroll
            for (int k = 0; k < PTS; k++) {
                const int n = cur_nbase + k * THREADS + tid;
                const float* p = P + ((size_t)cur_b * Nc + n) * 3;
                const float ax = p[0], ay = p[1], az = p[2];
                axp[k] = pk2(ax, ax);
                ayp[k] = pk2(ay, ay);
                azp[k] = pk2(az, az);
                n1s[k] = fmaf(ax, ax, fmaf(ay, ay, az * az));
                eminE[k] = CUDART_INF_F;
                eminO[k] = CUDART_INF_F;
            }
        }

        // compute CURRENT buffer
        const ulonglong2* sp = reinterpret_cast<const ulonglong2*>(tile[buf]);
#pragma unroll 8
        for (int jj = 0; jj < JP; jj++) {
            const ulonglong2 c0 = sp[2 * jj];       // {bx2_e,bx2_o} {by2_e,by2_o}
            const ulonglong2 c1 = sp[2 * jj + 1];   // {bz2_e,bz2_o} {n2_e,n2_o}
#pragma unroll
            for (int k = 0; k < PTS; k++) {
                unsigned long long e = ffma2(axp[k], c0.x, c1.y);
                e = ffma2(ayp[k], c0.y, e);
                e = ffma2(azp[k], c1.x, e);
                float flo, fhi;
                upk2(e, flo, fhi);
                eminE[k] = fminf(eminE[k], flo);
                eminO[k] = fminf(eminO[k], fhi);
            }
        }
    }

    if (cur_ach >= 0) {                  // final flush
        float* __restrict__ outd = cur_dir ? dist2 : dist1;
#pragma unroll
        for (int k = 0; k < PTS; k++) {
            const int n = cur_nbase + k * THREADS + tid;
            const float e = fminf(eminE[k], eminO[k]);
            const float d = fmaxf(n1s[k] + e, 0.0f);
            atomicMin((int*)&outd[(size_t)cur_b * Nc + n], __float_as_int(d));
        }
    }
}

// ---- deterministic 2-stage loss reduction ----
__device__ float g_partials[128];

__global__ void __launch_bounds__(256)
sum_stage1(const float* __restrict__ dists)   // dists = out+1, length 2*B*N
{
    __shared__ float red[256];
    const int tid = threadIdx.x;
    const int base = blockIdx.x * 1024;
    float s = 0.0f;
#pragma unroll
    for (int i = 0; i < 4; i++) s += dists[base + i * 256 + tid];
    red[tid] = s;
    __syncthreads();
    for (int w = 128; w > 0; w >>= 1) {
        if (tid < w) red[tid] += red[tid + w];
        __syncthreads();
    }
    if (tid == 0) g_partials[blockIdx.x] = red[0];
}

__global__ void __launch_bounds__(128)
sum_stage2(float* __restrict__ out)
{
    __shared__ float red[128];
    const int tid = threadIdx.x;
    red[tid] = g_partials[tid];
    __syncthreads();
    for (int w = 64; w > 0; w >>= 1) {
        if (tid < w) red[tid] += red[tid + w];
        __syncthreads();
    }
    if (tid == 0) out[0] = red[0] * (1.0f / (float)(Bc * Nc));
}

extern "C" void kernel_launch(void* const* d_in, const int* in_sizes, int n_in,
                              void* d_out, int out_size)
{
    const float* x1 = (const float*)d_in[0];
    const float* x2 = (const float*)d_in[1];
    float* out = (float*)d_out;
    float* dist1 = out + 1;
    float* dist2 = out + 1 + Bc * Nc;

    // Sentinel-fill dist arrays: 0x7F7F7F7F = 3.39e38 > any real sq-distance.
    cudaMemsetAsync(out + 1, 0x7F, (size_t)2 * Bc * Nc * sizeof(float));

    chamfer_pass_kernel<<<GRID, THREADS>>>(x1, x2, dist1, dist2);

    sum_stage1<<<128, 256>>>(out + 1);
    sum_stage2<<<1, 128>>>(out);
}